// round 3
// baseline (speedup 1.0000x reference)
#include <cuda_runtime.h>

// PWLU channelwise activation, scalar bounds ±2.3, n_points=7 (n_regions=6).
// x: [B=64, C=256, H=56, W=56] fp32; points: [C,7]; left_diffs/right_diffs: [C].
// out[b,c,h,w] = fp[c][r] + (xn - r) * df[c][r]
//   xn = (x - sim_left) / region_len ;  r = (int)clip(xn, 0, 7.007)
//
// R2: each block processes GROUP_B=4 batch-slices of ONE channel: the 8-entry
// smem table is built once and reused; 4x fewer CTAs / barriers / waves.

#define BOUND_F 2.3f
#define N_POINTS 7
#define N_REGIONS 6
#define C_DIM 256
#define HW 3136            // 56*56
#define HW4 784            // HW/4 float4 per slice
#define THREADS 256
#define GROUP_B 4
#define B_DIM 64

__global__ __launch_bounds__(THREADS)
void pwlu_kernel(const float* __restrict__ x,
                 const float* __restrict__ points,
                 const float* __restrict__ left_diffs,
                 const float* __restrict__ right_diffs,
                 float* __restrict__ out) {
    const int bx  = blockIdx.x;             // 0 .. C*(B/GROUP_B)-1
    const int c   = bx & (C_DIM - 1);
    const int g   = bx >> 8;                // batch-group index
    const int tid = threadIdx.x;

    // Per-channel (false_point, diff) table in shared memory, built once.
    __shared__ float2 tab[8];               // tab[r] = {fp[r], df[r]}
    if (tid < 8) {
        const float* p = points + c * N_POINTS;
        float fp, df;
        if (tid == 0)            { df = left_diffs[c];  fp = p[0] - df; }
        else if (tid == N_POINTS){ df = right_diffs[c]; fp = p[N_POINTS - 1]; }
        else                     { df = p[tid] - p[tid - 1]; fp = p[tid - 1]; }
        tab[tid] = make_float2(fp, df);
    }
    __syncthreads();

    const float region_len = (2.0f * BOUND_F) / (float)N_REGIONS;
    const float inv_rl     = (float)N_REGIONS / (2.0f * BOUND_F);
    const float sim_left   = -BOUND_F - region_len;
    const float clip_hi    = (float)(N_REGIONS + 1) * 1.001f;   // 7.007

    auto pwlu1 = [&](float xv) -> float {
        float xn = (xv - sim_left) * inv_rl;
        float rf = fminf(fmaxf(xn, 0.0f), clip_hi);
        int   r  = __float2int_rz(rf);
        float d  = xn - (float)r;
        float2 t = tab[r];
        return fmaf(d, t.y, t.x);
    };
    auto pwlu4 = [&](float4 v) -> float4 {
        float4 r;
        r.x = pwlu1(v.x); r.y = pwlu1(v.y);
        r.z = pwlu1(v.z); r.w = pwlu1(v.w);
        return r;
    };

    #pragma unroll
    for (int j = 0; j < GROUP_B; j++) {
        const int b = g * GROUP_B + j;
        const size_t base = ((size_t)b * C_DIM + c) * HW;
        const float4* __restrict__ xin = reinterpret_cast<const float4*>(x + base);
        float4* __restrict__ o         = reinterpret_cast<float4*>(out + base);

        // 784 float4: tid, +256, +512 always valid; +768 valid for tid<16.
        // Front-batch the loads for MLP, streaming cache policy (no reuse).
        float4 v0 = __ldcs(&xin[tid]);
        float4 v1 = __ldcs(&xin[tid + 256]);
        float4 v2 = __ldcs(&xin[tid + 512]);
        float4 v3;
        const bool has3 = (tid < HW4 - 768);
        if (has3) v3 = __ldcs(&xin[tid + 768]);

        __stcs(&o[tid],       pwlu4(v0));
        __stcs(&o[tid + 256], pwlu4(v1));
        __stcs(&o[tid + 512], pwlu4(v2));
        if (has3) __stcs(&o[tid + 768], pwlu4(v3));
    }
}

extern "C" void kernel_launch(void* const* d_in, const int* in_sizes, int n_in,
                              void* d_out, int out_size) {
    const float* x  = (const float*)d_in[0];
    const float* p  = (const float*)d_in[1];
    const float* ld = (const float*)d_in[2];
    const float* rd = (const float*)d_in[3];
    float* out = (float*)d_out;

    const int n_blocks = C_DIM * (B_DIM / GROUP_B);   // 4096
    pwlu_kernel<<<n_blocks, THREADS>>>(x, p, ld, rd, out);
}